// round 5
// baseline (speedup 1.0000x reference)
#include <cuda_runtime.h>
#include <cstdint>

// NeuralHMM forward, B=32, T=4096, K=16 — 3-phase chunked linear-space scan.
// C=16 timesteps/chunk -> 8192 chunks (2 per warp via half-warps), 1024 blocks.

#define FULLM 0xffffffffu

constexpr int B_ = 32, T_ = 4096, K_ = 16, C_ = 16, NCH = T_ / C_;   // NCH = 256
constexpr int NCHUNKS = B_ * NCH;                                     // 8192
constexpr float RHO = 0.001f;
constexpr float CLIPV = 1e-10f;

__device__ __align__(16) float g_chunkM[NCHUNKS][K_][K_]; // [chunk][k][i] = M[i][k]
__device__ __align__(16) float g_carry[NCHUNKS][K_];      // UNNORMALIZED alpha entering chunk j>=1

constexpr size_t N_BTK = (size_t)B_ * T_ * K_;
constexpr size_t N_BT  = (size_t)B_ * T_;
constexpr size_t OFF_LB = N_BTK;
constexpr size_t OFF_LZ = 2 * N_BTK;
constexpr size_t OFF_A  = 2 * N_BTK + N_BT;

// ---------------------------------------------------------------------------
// Phase 1: chunk transfer matrices + A output. 2 chunks/warp, lane owns row i.
// ---------------------------------------------------------------------------
__global__ __launch_bounds__(128) void k_chunkmats(
    const float* __restrict__ em, const float* __restrict__ bp,
    float* __restrict__ out)
{
    const int gwarp = (blockIdx.x * blockDim.x + threadIdx.x) >> 5;
    const int lane  = threadIdx.x & 31;
    const int i     = lane & 15;
    const int chunk = gwarp * 2 + (lane >> 4);
    const unsigned hm = 0xffffu << (lane & 16);
    const int b  = chunk >> 8;           // /NCH (256)
    const int j  = chunk & (NCH - 1);
    const int t0 = j * C_;
    const size_t bt0 = (size_t)b * T_ + t0;

    float* __restrict__ Abase = out + OFF_A + bt0 * (size_t)(K_ * K_);
    const float* __restrict__ embase = em + bt0 * K_;

    // --- A-write one-hot masks over an 8-float window covering cols i-1..i+1 ---
    int g_lo = (i <= 1) ? 0 : ((i - 1) >> 2);
    if (g_lo > 2) g_lo = 2;
    const int p = (i == 0) ? -1 : (i - 1) - g_lo * 4;
    float mr[8], md[8], me[8];
#pragma unroll
    for (int c = 0; c < 8; c++) {
        mr[c] = (c == p)     ? 1.0f : 0.0f;
        md[c] = (c == p + 1) ? 1.0f : 0.0f;
        me[c] = (c == p + 2) ? 1.0f : 0.0f;
    }
    const int zg0 = (g_lo + 2) & 3, zg1 = (g_lo + 3) & 3;
    const float4 zero4 = make_float4(0.f, 0.f, 0.f, 0.f);

    // --- upfront bp (16 values per chunk via 1 reg + shfl) ---
    const float bpA = __ldg(bp + bt0 + i);

    // --- em ring prefetch (lane's own k=i element), depth 4 ---
    float er[4];
#pragma unroll
    for (int u = 0; u < 4; u++) er[u] = __ldg(embase + u * K_ + i);

    float m[K_];
#pragma unroll
    for (int k = 0; k < K_; k++) m[k] = (k == i) ? 1.0f : 0.0f;
    float rs = 1.0f;

#pragma unroll 4
    for (int s = 0; s < C_; s++) {
        const float emraw = er[s & 3];
        if (s + 4 < C_) er[s & 3] = __ldg(embase + (s + 4) * K_ + i);

        const float bpv = __shfl_sync(hm, bpA, s, 16);
        const float eta = fminf(fmaxf(0.02f + 0.33f * bpv, 0.001f), 0.95f);
        const float d0  = 1.0f - eta;
        const float dm  = fmaxf((1.0f - eta) - RHO, 0.01f);
        const float d15 = 1.0f - RHO;
        const float inv0  = __fdividef(1.0f, fmaxf(d0 + eta, 1e-8f));
        const float invm  = __fdividef(1.0f, fmaxf((RHO + dm) + eta, 1e-8f));
        const float inv15 = __fdividef(1.0f, fmaxf(RHO + d15, 1e-8f));

        // ---- A row i write ----
        {
            const float invr = (i == 0) ? inv0 : (i == 15 ? inv15 : invm);
            const float dv = ((i == 0) ? d0 : (i == 15 ? d15 : dm)) * invr;
            const float ev = eta * invr;
            const float rv = RHO * invr;
            float w[8];
#pragma unroll
            for (int c = 0; c < 8; c++)
                w[c] = fmaf(mr[c], rv, fmaf(md[c], dv, me[c] * ev));
            float4* dst = reinterpret_cast<float4*>(Abase + (size_t)s * 256 + i * 16);
            __stcs(dst + zg0, zero4);
            __stcs(dst + zg1, zero4);
            __stcs(dst + g_lo,     make_float4(w[0], w[1], w[2], w[3]));
            __stcs(dst + g_lo + 1, make_float4(w[4], w[5], w[6], w[7]));
        }

        // ---- compose (t=0 is init, not a transition) ----
        if (t0 + s > 0) {
            const float e_own = __expf(emraw);
            const float up1   = eta * inv0;
            const float upm   = eta * invm;
            const float dia0  = d0  * inv0;
            const float diam  = dm  * invm;
            const float dia15 = d15 * inv15;
            const float dnm   = RHO * invm;
            const float dn14  = RHO * inv15;
            const float bg    = CLIPV * rs;   // background approx (rel err <= 3e-7)
            float rs_new = 0.0f, prev = 0.0f;
#pragma unroll
            for (int k = 0; k < 16; k++) {
                const float cur = m[k];
                const float nxt = (k < 15) ? m[k + 1] : 0.0f;
                const float up  = (k == 0) ? 0.0f : (k == 1 ? up1 : upm);
                const float di  = (k == 0) ? dia0 : (k == 15 ? dia15 : diam);
                const float dn  = (k >= 14) ? (k == 14 ? dn14 : 0.0f) : dnm;
                float v = fmaf(prev, up, bg);
                v = fmaf(cur, di, v);
                v = fmaf(nxt, dn, v);
                v *= __shfl_sync(hm, e_own, k, 16);
                m[k] = v;
                rs_new += v;
                prev = cur;
            }
            rs = rs_new;
            if ((s & 7) == 7) {
                float mx = m[0];
#pragma unroll
                for (int k = 1; k < 16; k++) mx = fmaxf(mx, m[k]);
#pragma unroll
                for (int o = 1; o < 16; o <<= 1)
                    mx = fmaxf(mx, __shfl_xor_sync(hm, mx, o, 16));
                const float sc = __fdividef(1.0f, mx);
#pragma unroll
                for (int k = 0; k < 16; k++) m[k] *= sc;
                rs *= sc;
            }
        }
    }

    float* dstM = &g_chunkM[chunk][0][0];
#pragma unroll
    for (int k = 0; k < 16; k++) dstM[k * 16 + i] = m[k];
}

// ---------------------------------------------------------------------------
// Phase 2: per-batch scan over chunk matrices (one warp per batch).
// Unnormalized (scale-invariant); rescale by max every 8 hops.
// Depth-4 register prefetch ring covers L2 latency.
// ---------------------------------------------------------------------------
__global__ void k_scan()
{
    const int b    = blockIdx.x;
    const int lane = threadIdx.x;
    const int k    = lane & 15;

    // column k of chunk j lives at float4 index j*64 + k*4 + q
    const float4* __restrict__ base =
        reinterpret_cast<const float4*>(&g_chunkM[(size_t)b * NCH][0][0]);

    float4 r[4][4];
#pragma unroll
    for (int u = 0; u < 4; u++) {
#pragma unroll
        for (int q = 0; q < 4; q++)
            r[u][q] = __ldg(base + u * 64 + k * 4 + q);
    }

    float v = (k == 0) ? 1.0f : 0.0f;

    for (int j = 0; j < NCH; j++) {
        const int slot = j & 3;
        const float4 c0 = r[slot][0], c1 = r[slot][1];
        const float4 c2 = r[slot][2], c3 = r[slot][3];
        if (j + 4 < NCH) {
            const float4* nb = base + (j + 4) * 64 + k * 4;
            r[slot][0] = __ldg(nb + 0);
            r[slot][1] = __ldg(nb + 1);
            r[slot][2] = __ldg(nb + 2);
            r[slot][3] = __ldg(nb + 3);
        }
        float a0 = 0.f, a1 = 0.f, a2 = 0.f, a3 = 0.f;
        a0 = fmaf(__shfl_sync(FULLM, v, 0,  16), c0.x, a0);
        a0 = fmaf(__shfl_sync(FULLM, v, 1,  16), c0.y, a0);
        a0 = fmaf(__shfl_sync(FULLM, v, 2,  16), c0.z, a0);
        a0 = fmaf(__shfl_sync(FULLM, v, 3,  16), c0.w, a0);
        a1 = fmaf(__shfl_sync(FULLM, v, 4,  16), c1.x, a1);
        a1 = fmaf(__shfl_sync(FULLM, v, 5,  16), c1.y, a1);
        a1 = fmaf(__shfl_sync(FULLM, v, 6,  16), c1.z, a1);
        a1 = fmaf(__shfl_sync(FULLM, v, 7,  16), c1.w, a1);
        a2 = fmaf(__shfl_sync(FULLM, v, 8,  16), c2.x, a2);
        a2 = fmaf(__shfl_sync(FULLM, v, 9,  16), c2.y, a2);
        a2 = fmaf(__shfl_sync(FULLM, v, 10, 16), c2.z, a2);
        a2 = fmaf(__shfl_sync(FULLM, v, 11, 16), c2.w, a2);
        a3 = fmaf(__shfl_sync(FULLM, v, 12, 16), c3.x, a3);
        a3 = fmaf(__shfl_sync(FULLM, v, 13, 16), c3.y, a3);
        a3 = fmaf(__shfl_sync(FULLM, v, 14, 16), c3.z, a3);
        a3 = fmaf(__shfl_sync(FULLM, v, 15, 16), c3.w, a3);
        v = (a0 + a1) + (a2 + a3);

        if (j + 1 < NCH && lane < 16) g_carry[b * NCH + j + 1][k] = v;

        if ((j & 7) == 7) {
            float mx = v;
#pragma unroll
            for (int o = 1; o < 16; o <<= 1)
                mx = fmaxf(mx, __shfl_xor_sync(FULLM, mx, o, 16));
            v *= __fdividef(1.0f, mx);
        }
    }
}

// ---------------------------------------------------------------------------
// Phase 3: replay each chunk. 2 chunks/warp, lane owns state k.
// Carry is normalized ON ENTRY (alpha /= S) so lZ = log(z) is exact.
// ---------------------------------------------------------------------------
__global__ __launch_bounds__(128) void k_replay(
    const float* __restrict__ em, const float* __restrict__ bp,
    const float* __restrict__ msk, float* __restrict__ out)
{
    const int gwarp = (blockIdx.x * blockDim.x + threadIdx.x) >> 5;
    const int lane  = threadIdx.x & 31;
    const int k     = lane & 15;
    const int chunk = gwarp * 2 + (lane >> 4);
    const unsigned hm = 0xffffu << (lane & 16);
    const int b  = chunk >> 8;
    const int j  = chunk & (NCH - 1);
    const int t0 = j * C_;
    const size_t bt0 = (size_t)b * T_ + t0;

    float* __restrict__ bel = out;
    float* __restrict__ lgb = out + OFF_LB;
    float* __restrict__ lgz = out + OFF_LZ;

    const float* __restrict__ embase = em + bt0 * K_;

    const float bpv0 = __ldg(bp  + bt0 + k);
    const float mv0  = __ldg(msk + bt0 + k);

    float er[4];
#pragma unroll
    for (int u = 0; u < 4; u++) er[u] = __ldg(embase + u * K_ + k);

    float alpha;
    if (j == 0) {
        alpha = (k == 0) ? 1.0f : 0.0f;
    } else {
        alpha = g_carry[chunk][k];
        float ss = alpha;
#pragma unroll
        for (int o = 1; o < 16; o <<= 1) ss += __shfl_xor_sync(hm, ss, o, 16);
        alpha *= __fdividef(1.0f, ss);     // normalize carry: sum(alpha) == 1
    }

#pragma unroll 4
    for (int s = 0; s < C_; s++) {
        const float emv = er[s & 3];
        if (s + 4 < C_) er[s & 3] = __ldg(embase + (s + 4) * K_ + k);

        const size_t t = bt0 + s;
        const float bpv = __shfl_sync(hm, bpv0, s, 16);
        const float mv  = __shfl_sync(hm, mv0,  s, 16);

        if (s == 0 && j == 0) {
            const float em00 = __shfl_sync(hm, emv, 0, 16);
            const float lb0 = (k == 0) ? 0.0f
                          : ((mv > 0.5f) ? ((-1.0e6f + emv) - em00) : -1.0e6f);
            bel[t * K_ + k] = alpha;
            lgb[t * K_ + k] = lb0;
            if (k == 0) lgz[t] = mv * em00;
            continue;
        }

        const float eta = fminf(fmaxf(0.02f + 0.33f * bpv, 0.001f), 0.95f);
        const float d0  = 1.0f - eta;
        const float dm  = fmaxf((1.0f - eta) - RHO, 0.01f);
        const float inv0  = __fdividef(1.0f, fmaxf(d0 + eta, 1e-8f));
        const float invm  = __fdividef(1.0f, fmaxf((RHO + dm) + eta, 1e-8f));
        const float inv15 = __fdividef(1.0f, fmaxf(RHO + (1.0f - RHO), 1e-8f));

        const float a_up = eta * ((k == 1) ? inv0 : invm);
        const float a_di = (k == 0) ? d0 * inv0
                          : (k == 15 ? (1.0f - RHO) * inv15 : dm * invm);
        const float a_dn = RHO * ((k == 14) ? inv15 : invm);

        const float am1 = __shfl_up_sync(hm, alpha, 1, 16);
        const float ap1 = __shfl_down_sync(hm, alpha, 1, 16);
        const float c_m1 = (k > 0)  ? am1 : 0.0f;
        const float c_p1 = (k < 15) ? ap1 : 0.0f;

        float pred = fmaf(c_m1, a_up, CLIPV);      // background (sum(alpha)==1)
        pred = fmaf(alpha, a_di, pred);
        pred = fmaf(c_p1, a_dn, pred);
        const float lj  = pred * __expf(emv);
        const float llj = __logf(lj);

        float z = lj;
#pragma unroll
        for (int o = 1; o < 16; o <<= 1) z += __shfl_xor_sync(hm, z, o, 16);

        const float lZ = __logf(z);
        float lgbv;
        if (mv > 0.5f) {
            alpha = __fdividef(lj, z);
            lgbv  = llj - lZ;
        } else {
            lgbv  = __logf(alpha);
        }

        bel[t * K_ + k] = alpha;
        lgb[t * K_ + k] = lgbv;
        if (k == 0) lgz[t] = mv * lZ;
    }
}

extern "C" void kernel_launch(void* const* d_in, const int* in_sizes, int n_in,
                              void* d_out, int out_size)
{
    const float* em  = (const float*)d_in[0];
    const float* bp  = (const float*)d_in[1];
    const float* msk = (const float*)d_in[2];
    float* out = (float*)d_out;

    k_chunkmats<<<NCHUNKS / 8, 128>>>(em, bp, out);   // 1024 blocks
    k_scan<<<B_, 32>>>();
    k_replay<<<NCHUNKS / 8, 128>>>(em, bp, msk, out); // 1024 blocks
}

// round 6
// speedup vs baseline: 2.0099x; 2.0099x over previous
#include <cuda_runtime.h>
#include <cstdint>

// NeuralHMM forward, B=32, T=4096, K=16 — 3-phase chunked linear-space scan.
// C=32 timesteps/chunk -> 4096 chunks (2 per warp via half-warps), 512 blocks.
// All transition-row sums are exactly 1 (to ulp), so row normalization is a
// no-op and every divide is removed.

#define FULLM 0xffffffffu

constexpr int B_ = 32, T_ = 4096, K_ = 16, C_ = 32, NCH = T_ / C_;   // NCH = 128
constexpr int NCHUNKS = B_ * NCH;                                     // 4096
constexpr float RHO = 0.001f;
constexpr float D15 = 1.0f - RHO;      // 0.999
constexpr float CLIPV = 1e-10f;

__device__ __align__(16) float g_chunkM[NCHUNKS][K_][K_]; // [chunk][k][i] = M[i][k]
__device__ __align__(16) float g_carry[NCHUNKS][K_];      // UNNORMALIZED alpha entering chunk j>=1

constexpr size_t N_BTK = (size_t)B_ * T_ * K_;
constexpr size_t N_BT  = (size_t)B_ * T_;
constexpr size_t OFF_LB = N_BTK;
constexpr size_t OFF_LZ = 2 * N_BTK;
constexpr size_t OFF_A  = 2 * N_BTK + N_BT;

// ---------------------------------------------------------------------------
// Phase 1: chunk transfer matrices + A output. 2 chunks/warp, lane owns row i.
// ---------------------------------------------------------------------------
__global__ __launch_bounds__(128) void k_chunkmats(
    const float* __restrict__ em, const float* __restrict__ bp,
    float* __restrict__ out)
{
    const int gwarp = (blockIdx.x * blockDim.x + threadIdx.x) >> 5;
    const int lane  = threadIdx.x & 31;
    const int i     = lane & 15;
    const int chunk = gwarp * 2 + (lane >> 4);
    const unsigned hm = 0xffffu << (lane & 16);
    const int b  = chunk >> 7;           // /NCH (128)
    const int j  = chunk & (NCH - 1);
    const int t0 = j * C_;
    const size_t bt0 = (size_t)b * T_ + t0;

    float* __restrict__ Abase = out + OFF_A + bt0 * (size_t)(K_ * K_);
    const float* __restrict__ embase = em + bt0 * K_;

    // --- A-write one-hot masks over an 8-float window covering cols i-1..i+1 ---
    int g_lo = (i <= 1) ? 0 : ((i - 1) >> 2);
    if (g_lo > 2) g_lo = 2;
    const int p = (i == 0) ? -1 : (i - 1) - g_lo * 4;
    float mrRHO[8], md[8], me[8];
#pragma unroll
    for (int c = 0; c < 8; c++) {
        mrRHO[c] = (c == p)     ? RHO  : 0.0f;   // rho premultiplied (const)
        md[c]    = (c == p + 1) ? 1.0f : 0.0f;
        me[c]    = (c == p + 2) ? 1.0f : 0.0f;
    }
    const int zg0 = (g_lo + 2) & 3, zg1 = (g_lo + 3) & 3;
    const float4 zero4 = make_float4(0.f, 0.f, 0.f, 0.f);

    // --- upfront bp (32 values per chunk via 2 regs + shfl) ---
    const float bpA = __ldg(bp + bt0 + i);
    const float bpB = __ldg(bp + bt0 + 16 + i);

    // --- em ring prefetch (lane's own k=i element), depth 4 ---
    float er[4];
#pragma unroll
    for (int u = 0; u < 4; u++) er[u] = __ldg(embase + u * K_ + i);

    float m[K_];
#pragma unroll
    for (int k = 0; k < K_; k++) m[k] = (k == i) ? 1.0f : 0.0f;
    float rs = 1.0f;

#pragma unroll 4
    for (int s = 0; s < C_; s++) {
        const float emraw = er[s & 3];
        if (s + 4 < C_) er[s & 3] = __ldg(embase + (s + 4) * K_ + i);

        const float bpv = __shfl_sync(hm, (s < 16) ? bpA : bpB, s & 15, 16);
        const float eta = fminf(fmaxf(fmaf(0.33f, bpv, 0.02f), 0.001f), 0.95f);
        const float d0  = 1.0f - eta;
        const float dm  = d0 - RHO;           // clamp at 0.01 never binds (eta<=0.95)

        // ---- A row i write (row sums == 1, no normalization) ----
        {
            const float dv = (i == 0) ? d0 : (i == 15 ? D15 : dm);
            float w[8];
#pragma unroll
            for (int c = 0; c < 8; c++)
                w[c] = fmaf(md[c], dv, fmaf(me[c], eta, mrRHO[c]));
            float4* dst = reinterpret_cast<float4*>(Abase + (size_t)s * 256 + i * 16);
            __stcs(dst + zg0, zero4);
            __stcs(dst + zg1, zero4);
            __stcs(dst + g_lo,     make_float4(w[0], w[1], w[2], w[3]));
            __stcs(dst + g_lo + 1, make_float4(w[4], w[5], w[6], w[7]));
        }

        // ---- compose (t=0 is init, not a transition) ----
        if (t0 + s > 0) {
            const float e_own = __expf(emraw);
            const float bg    = CLIPV * rs;   // background (rel err <= 3e-7)
            float rs_new = 0.0f, prev = 0.0f;
#pragma unroll
            for (int k = 0; k < 16; k++) {
                const float cur = m[k];
                const float nxt = (k < 15) ? m[k + 1] : 0.0f;
                float v;
                if (k == 0)       v = fmaf(cur, d0, bg);
                else if (k == 15) v = fmaf(prev, eta, fmaf(cur, D15, bg));
                else              v = fmaf(prev, eta, fmaf(cur, dm, bg));
                if (k < 15)       v = fmaf(nxt, RHO, v);
                v *= __shfl_sync(hm, e_own, k, 16);
                m[k] = v;
                rs_new += v;
                prev = cur;
            }
            rs = rs_new;
            if ((s & 7) == 7) {
                float mx = m[0];
#pragma unroll
                for (int k = 1; k < 16; k++) mx = fmaxf(mx, m[k]);
#pragma unroll
                for (int o = 1; o < 16; o <<= 1)
                    mx = fmaxf(mx, __shfl_xor_sync(hm, mx, o, 16));
                const float sc = __frcp_rn(mx);
#pragma unroll
                for (int k = 0; k < 16; k++) m[k] *= sc;
                rs *= sc;
            }
        }
    }

    float* dstM = &g_chunkM[chunk][0][0];
#pragma unroll
    for (int k = 0; k < 16; k++) dstM[k * 16 + i] = m[k];
}

// ---------------------------------------------------------------------------
// Phase 2: per-batch scan over chunk matrices (one warp per batch).
// Depth-4 software pipeline with STATICALLY-indexed slot arrays (no spills).
// ---------------------------------------------------------------------------
__device__ __forceinline__ float scan_hop(float v, const float4* c)
{
    float a0 = 0.f, a1 = 0.f, a2 = 0.f, a3 = 0.f;
    a0 = fmaf(__shfl_sync(FULLM, v, 0,  16), c[0].x, a0);
    a0 = fmaf(__shfl_sync(FULLM, v, 1,  16), c[0].y, a0);
    a0 = fmaf(__shfl_sync(FULLM, v, 2,  16), c[0].z, a0);
    a0 = fmaf(__shfl_sync(FULLM, v, 3,  16), c[0].w, a0);
    a1 = fmaf(__shfl_sync(FULLM, v, 4,  16), c[1].x, a1);
    a1 = fmaf(__shfl_sync(FULLM, v, 5,  16), c[1].y, a1);
    a1 = fmaf(__shfl_sync(FULLM, v, 6,  16), c[1].z, a1);
    a1 = fmaf(__shfl_sync(FULLM, v, 7,  16), c[1].w, a1);
    a2 = fmaf(__shfl_sync(FULLM, v, 8,  16), c[2].x, a2);
    a2 = fmaf(__shfl_sync(FULLM, v, 9,  16), c[2].y, a2);
    a2 = fmaf(__shfl_sync(FULLM, v, 10, 16), c[2].z, a2);
    a2 = fmaf(__shfl_sync(FULLM, v, 11, 16), c[2].w, a2);
    a3 = fmaf(__shfl_sync(FULLM, v, 12, 16), c[3].x, a3);
    a3 = fmaf(__shfl_sync(FULLM, v, 13, 16), c[3].y, a3);
    a3 = fmaf(__shfl_sync(FULLM, v, 14, 16), c[3].z, a3);
    a3 = fmaf(__shfl_sync(FULLM, v, 15, 16), c[3].w, a3);
    return (a0 + a1) + (a2 + a3);
}

__global__ void k_scan()
{
    const int b    = blockIdx.x;
    const int lane = threadIdx.x;
    const int k    = lane & 15;

    // column k of chunk j lives at float4 index j*64 + k*4 + q
    const float4* __restrict__ base =
        reinterpret_cast<const float4*>(&g_chunkM[(size_t)b * NCH][0][0]) + k * 4;

    float4 s0[4], s1[4], s2[4], s3[4];
#pragma unroll
    for (int q = 0; q < 4; q++) {
        s0[q] = __ldg(base + 0 * 64 + q);
        s1[q] = __ldg(base + 1 * 64 + q);
        s2[q] = __ldg(base + 2 * 64 + q);
        s3[q] = __ldg(base + 3 * 64 + q);
    }

    float v = (k == 0) ? 1.0f : 0.0f;
    float* __restrict__ carry = &g_carry[(size_t)b * NCH][0];

    for (int jb = 0; jb < NCH; jb += 4) {
        // j = jb
        v = scan_hop(v, s0);
        if (lane < 16) carry[(jb + 1) * K_ + k] = v;
        if (jb + 4 < NCH) {
#pragma unroll
            for (int q = 0; q < 4; q++) s0[q] = __ldg(base + (jb + 4) * 64 + q);
        }
        // j = jb+1
        v = scan_hop(v, s1);
        if (lane < 16) carry[(jb + 2) * K_ + k] = v;
        if (jb + 5 < NCH) {
#pragma unroll
            for (int q = 0; q < 4; q++) s1[q] = __ldg(base + (jb + 5) * 64 + q);
        }
        // j = jb+2
        v = scan_hop(v, s2);
        if (lane < 16) carry[(jb + 3) * K_ + k] = v;
        if (jb + 6 < NCH) {
#pragma unroll
            for (int q = 0; q < 4; q++) s2[q] = __ldg(base + (jb + 6) * 64 + q);
        }
        // j = jb+3
        v = scan_hop(v, s3);
        if (jb + 4 < NCH) {
            if (lane < 16) carry[(jb + 4) * K_ + k] = v;
#pragma unroll
            for (int q = 0; q < 4; q++) s3[q] = __ldg(base + (jb + 7) * 64 + q);
        }
        // rescale every 8 chunks: j = jb+3 ≡ 7 (mod 8)  <=>  jb ≡ 4 (mod 8)
        if ((jb & 7) == 4) {
            float mx = v;
#pragma unroll
            for (int o = 1; o < 16; o <<= 1)
                mx = fmaxf(mx, __shfl_xor_sync(FULLM, mx, o, 16));
            v *= __frcp_rn(mx);
        }
    }
}

// ---------------------------------------------------------------------------
// Phase 3: replay each chunk. 2 chunks/warp, lane owns state k.
// Carry normalized ON ENTRY (sum == 1), so lZ = log(z) is exact.
// ---------------------------------------------------------------------------
__global__ __launch_bounds__(128) void k_replay(
    const float* __restrict__ em, const float* __restrict__ bp,
    const float* __restrict__ msk, float* __restrict__ out)
{
    const int gwarp = (blockIdx.x * blockDim.x + threadIdx.x) >> 5;
    const int lane  = threadIdx.x & 31;
    const int k     = lane & 15;
    const int chunk = gwarp * 2 + (lane >> 4);
    const unsigned hm = 0xffffu << (lane & 16);
    const int b  = chunk >> 7;
    const int j  = chunk & (NCH - 1);
    const int t0 = j * C_;
    const size_t bt0 = (size_t)b * T_ + t0;

    float* __restrict__ bel = out;
    float* __restrict__ lgb = out + OFF_LB;
    float* __restrict__ lgz = out + OFF_LZ;

    const float* __restrict__ embase = em + bt0 * K_;

    const float bpv0 = __ldg(bp  + bt0 + k);
    const float bpv1 = __ldg(bp  + bt0 + 16 + k);
    const float mv0  = __ldg(msk + bt0 + k);
    const float mv1  = __ldg(msk + bt0 + 16 + k);

    float er[4];
#pragma unroll
    for (int u = 0; u < 4; u++) er[u] = __ldg(embase + u * K_ + k);

    float alpha;
    if (j == 0) {
        alpha = (k == 0) ? 1.0f : 0.0f;
    } else {
        alpha = g_carry[chunk][k];
        float ss = alpha;
#pragma unroll
        for (int o = 1; o < 16; o <<= 1) ss += __shfl_xor_sync(hm, ss, o, 16);
        alpha *= __frcp_rn(ss);            // normalize carry: sum(alpha) == 1
    }

#pragma unroll 4
    for (int s = 0; s < C_; s++) {
        const float emv = er[s & 3];
        if (s + 4 < C_) er[s & 3] = __ldg(embase + (s + 4) * K_ + k);

        const size_t t = bt0 + s;
        const float bpv = __shfl_sync(hm, (s < 16) ? bpv0 : bpv1, s & 15, 16);
        const float mv  = __shfl_sync(hm, (s < 16) ? mv0  : mv1,  s & 15, 16);

        if (s == 0 && j == 0) {
            const float em00 = __shfl_sync(hm, emv, 0, 16);
            const float lb0 = (k == 0) ? 0.0f
                          : ((mv > 0.5f) ? ((-1.0e6f + emv) - em00) : -1.0e6f);
            bel[t * K_ + k] = alpha;
            lgb[t * K_ + k] = lb0;
            if (k == 0) lgz[t] = mv * em00;
            continue;
        }

        const float eta = fminf(fmaxf(fmaf(0.33f, bpv, 0.02f), 0.001f), 0.95f);
        const float d0  = 1.0f - eta;
        const float dm  = d0 - RHO;

        // incoming coefficients (row sums == 1; no divides)
        const float a_di = (k == 0) ? d0 : (k == 15 ? D15 : dm);

        const float am1 = __shfl_up_sync(hm, alpha, 1, 16);
        const float ap1 = __shfl_down_sync(hm, alpha, 1, 16);
        const float c_m1 = (k > 0)  ? am1 : 0.0f;
        const float c_p1 = (k < 15) ? ap1 : 0.0f;

        float pred = fmaf(c_m1, eta, CLIPV);       // background (sum(alpha)==1)
        pred = fmaf(alpha, a_di, pred);
        pred = fmaf(c_p1, RHO, pred);
        const float lj = pred * __expf(emv);

        float z = lj;
#pragma unroll
        for (int o = 1; o < 16; o <<= 1) z += __shfl_xor_sync(hm, z, o, 16);

        const float lZ = __logf(z);
        float lgbv;
        if (mv > 0.5f) {
            alpha = lj * __frcp_rn(z);
            lgbv  = __logf(alpha);
        } else {
            lgbv  = __logf(alpha);
        }

        bel[t * K_ + k] = alpha;
        lgb[t * K_ + k] = lgbv;
        if (k == 0) lgz[t] = mv * lZ;
    }
}

extern "C" void kernel_launch(void* const* d_in, const int* in_sizes, int n_in,
                              void* d_out, int out_size)
{
    const float* em  = (const float*)d_in[0];
    const float* bp  = (const float*)d_in[1];
    const float* msk = (const float*)d_in[2];
    float* out = (float*)d_out;

    k_chunkmats<<<NCHUNKS / 8, 128>>>(em, bp, out);   // 512 blocks
    k_scan<<<B_, 32>>>();
    k_replay<<<NCHUNKS / 8, 128>>>(em, bp, msk, out); // 512 blocks
}

// round 7
// speedup vs baseline: 2.9385x; 1.4620x over previous
#include <cuda_runtime.h>
#include <cstdint>

// NeuralHMM forward, B=32, T=4096, K=16 — 3-phase chunked linear-space scan.
// C=32 timesteps/chunk -> 4096 chunks (2 per warp via half-warps), 512 blocks.
// A entries are affine in eta: w = K0 + eta*K1 (lane-constant K0/K1), written
// with coalesced 256B-per-halfwarp stores. Scan uses a depth-8 static pipeline.

#define FULLM 0xffffffffu

constexpr int B_ = 32, T_ = 4096, K_ = 16, C_ = 32, NCH = T_ / C_;   // NCH = 128
constexpr int NCHUNKS = B_ * NCH;                                     // 4096
constexpr float RHO = 0.001f;
constexpr float D15 = 1.0f - RHO;      // 0.999
constexpr float CLIPV = 1e-10f;

__device__ __align__(16) float g_chunkM[NCHUNKS][K_][K_]; // [chunk][k][i] = M[i][k] (col-major)
__device__ __align__(16) float g_carry[NCHUNKS][K_];      // UNNORMALIZED alpha entering chunk j>=1

constexpr size_t N_BTK = (size_t)B_ * T_ * K_;
constexpr size_t N_BT  = (size_t)B_ * T_;
constexpr size_t OFF_LB = N_BTK;
constexpr size_t OFF_LZ = 2 * N_BTK;
constexpr size_t OFF_A  = 2 * N_BTK + N_BT;

// ---------------------------------------------------------------------------
// Phase 1: chunk transfer matrices + A output. 2 chunks/warp, lane owns row i
// for the compose; lane owns float4 slots {i,16+i,32+i,48+i} for the A write.
// ---------------------------------------------------------------------------
__global__ __launch_bounds__(128) void k_chunkmats(
    const float* __restrict__ em, const float* __restrict__ bp,
    float* __restrict__ out)
{
    const int gwarp = (blockIdx.x * blockDim.x + threadIdx.x) >> 5;
    const int lane  = threadIdx.x & 31;
    const int i     = lane & 15;
    const int chunk = gwarp * 2 + (lane >> 4);
    const unsigned hm = 0xffffu << (lane & 16);
    const int b  = chunk >> 7;           // /NCH (128)
    const int j  = chunk & (NCH - 1);
    const int t0 = j * C_;
    const size_t bt0 = (size_t)b * T_ + t0;

    float4* __restrict__ A4 =
        reinterpret_cast<float4*>(out + OFF_A + bt0 * (size_t)(K_ * K_));
    const float* __restrict__ embase = em + bt0 * K_;

    // --- affine A coefficients: entry = K0 + eta*K1, per lane's 4 slots ---
    float K0[4][4], K1[4][4];
#pragma unroll
    for (int u = 0; u < 4; u++) {
        const int r  = u * 4 + (i >> 2);
        const int cg = i & 3;
#pragma unroll
        for (int q = 0; q < 4; q++) {
            const int col = cg * 4 + q;
            float k0 = 0.f, k1 = 0.f;
            if (col == r - 1) k0 += RHO;
            if (col == r) {
                if (r == 0)       { k0 += 1.0f;       k1 -= 1.0f; }
                else if (r == 15) { k0 += D15; }
                else              { k0 += 1.0f - RHO; k1 -= 1.0f; }
            }
            if (col == r + 1 && r < 15) k1 += 1.0f;
            K0[u][q] = k0; K1[u][q] = k1;
        }
    }

    // --- upfront bp (32 values per chunk via 2 regs + shfl) ---
    const float bpA = __ldg(bp + bt0 + i);
    const float bpB = __ldg(bp + bt0 + 16 + i);

    // --- em ring prefetch (lane's own k=i element), depth 4 ---
    float er[4];
#pragma unroll
    for (int u = 0; u < 4; u++) er[u] = __ldg(embase + u * K_ + i);

    float m[K_];
#pragma unroll
    for (int k = 0; k < K_; k++) m[k] = (k == i) ? 1.0f : 0.0f;
    float rs = 1.0f;

#pragma unroll 4
    for (int s = 0; s < C_; s++) {
        const float emraw = er[s & 3];
        if (s + 4 < C_) er[s & 3] = __ldg(embase + (s + 4) * K_ + i);

        const float bpv = __shfl_sync(hm, (s < 16) ? bpA : bpB, s & 15, 16);
        const float eta = fminf(fmaxf(fmaf(0.33f, bpv, 0.02f), 0.001f), 0.95f);
        const float d0  = 1.0f - eta;
        const float dm  = d0 - RHO;

        // ---- A write: 4 coalesced float4 stores (256B contiguous/half-warp) ----
#pragma unroll
        for (int u = 0; u < 4; u++) {
            float4 w;
            w.x = fmaf(eta, K1[u][0], K0[u][0]);
            w.y = fmaf(eta, K1[u][1], K0[u][1]);
            w.z = fmaf(eta, K1[u][2], K0[u][2]);
            w.w = fmaf(eta, K1[u][3], K0[u][3]);
            __stcs(A4 + s * 64 + u * 16 + i, w);
        }

        // ---- compose (t=0 is init, not a transition) ----
        if (t0 + s > 0) {
            const float e_own = __expf(emraw);
            const float bg    = CLIPV * rs;   // background (rel err <= 3e-7)
            float rs_new = 0.0f, prev = 0.0f;
#pragma unroll
            for (int k = 0; k < 16; k++) {
                const float cur = m[k];
                const float nxt = (k < 15) ? m[k + 1] : 0.0f;
                float v;
                if (k == 0)       v = fmaf(cur, d0, bg);
                else if (k == 15) v = fmaf(prev, eta, fmaf(cur, D15, bg));
                else              v = fmaf(prev, eta, fmaf(cur, dm, bg));
                if (k < 15)       v = fmaf(nxt, RHO, v);
                v *= __shfl_sync(hm, e_own, k, 16);
                m[k] = v;
                rs_new += v;
                prev = cur;
            }
            rs = rs_new;
            if ((s & 7) == 7) {
                float mx = m[0];
#pragma unroll
                for (int k = 1; k < 16; k++) mx = fmaxf(mx, m[k]);
#pragma unroll
                for (int o = 1; o < 16; o <<= 1)
                    mx = fmaxf(mx, __shfl_xor_sync(hm, mx, o, 16));
                const float sc = __frcp_rn(mx);
#pragma unroll
                for (int k = 0; k < 16; k++) m[k] *= sc;
                rs *= sc;
            }
        }
    }

    float* dstM = &g_chunkM[chunk][0][0];
#pragma unroll
    for (int k = 0; k < 16; k++) dstM[k * 16 + i] = m[k];
}

// ---------------------------------------------------------------------------
// Phase 2: per-batch scan over chunk matrices (one warp per batch).
// Depth-8 software pipeline (statically-named slots; covers 262-cy L2 latency).
// ---------------------------------------------------------------------------
__device__ __forceinline__ float scan_hop(float v, const float4* c)
{
    float a0 = 0.f, a1 = 0.f, a2 = 0.f, a3 = 0.f;
    a0 = fmaf(__shfl_sync(FULLM, v, 0,  16), c[0].x, a0);
    a0 = fmaf(__shfl_sync(FULLM, v, 1,  16), c[0].y, a0);
    a0 = fmaf(__shfl_sync(FULLM, v, 2,  16), c[0].z, a0);
    a0 = fmaf(__shfl_sync(FULLM, v, 3,  16), c[0].w, a0);
    a1 = fmaf(__shfl_sync(FULLM, v, 4,  16), c[1].x, a1);
    a1 = fmaf(__shfl_sync(FULLM, v, 5,  16), c[1].y, a1);
    a1 = fmaf(__shfl_sync(FULLM, v, 6,  16), c[1].z, a1);
    a1 = fmaf(__shfl_sync(FULLM, v, 7,  16), c[1].w, a1);
    a2 = fmaf(__shfl_sync(FULLM, v, 8,  16), c[2].x, a2);
    a2 = fmaf(__shfl_sync(FULLM, v, 9,  16), c[2].y, a2);
    a2 = fmaf(__shfl_sync(FULLM, v, 10, 16), c[2].z, a2);
    a2 = fmaf(__shfl_sync(FULLM, v, 11, 16), c[2].w, a2);
    a3 = fmaf(__shfl_sync(FULLM, v, 12, 16), c[3].x, a3);
    a3 = fmaf(__shfl_sync(FULLM, v, 13, 16), c[3].y, a3);
    a3 = fmaf(__shfl_sync(FULLM, v, 14, 16), c[3].z, a3);
    a3 = fmaf(__shfl_sync(FULLM, v, 15, 16), c[3].w, a3);
    return (a0 + a1) + (a2 + a3);
}

#define SCAN_HOP_SLOT(S, J)                                                   \
    v = scan_hop(v, S);                                                       \
    if (lane < 16) carry[((J) + 1) * K_ + k] = v;                             \
    if ((J) + 8 < NCH) {                                                      \
        _Pragma("unroll")                                                     \
        for (int q = 0; q < 4; q++) S[q] = __ldg(base + ((J) + 8) * 64 + q);  \
    }

__global__ void k_scan()
{
    const int b    = blockIdx.x;
    const int lane = threadIdx.x;
    const int k    = lane & 15;

    // column k of chunk j lives at float4 index j*64 + k*4 + q
    const float4* __restrict__ base =
        reinterpret_cast<const float4*>(&g_chunkM[(size_t)b * NCH][0][0]) + k * 4;

    float4 s0[4], s1[4], s2[4], s3[4], s4[4], s5[4], s6[4], s7[4];
#pragma unroll
    for (int q = 0; q < 4; q++) {
        s0[q] = __ldg(base + 0 * 64 + q);
        s1[q] = __ldg(base + 1 * 64 + q);
        s2[q] = __ldg(base + 2 * 64 + q);
        s3[q] = __ldg(base + 3 * 64 + q);
        s4[q] = __ldg(base + 4 * 64 + q);
        s5[q] = __ldg(base + 5 * 64 + q);
        s6[q] = __ldg(base + 6 * 64 + q);
        s7[q] = __ldg(base + 7 * 64 + q);
    }

    float v = (k == 0) ? 1.0f : 0.0f;
    float* __restrict__ carry = &g_carry[(size_t)b * NCH][0];

    for (int jb = 0; jb < NCH; jb += 8) {
        SCAN_HOP_SLOT(s0, jb + 0)
        SCAN_HOP_SLOT(s1, jb + 1)
        SCAN_HOP_SLOT(s2, jb + 2)
        SCAN_HOP_SLOT(s3, jb + 3)
        SCAN_HOP_SLOT(s4, jb + 4)
        SCAN_HOP_SLOT(s5, jb + 5)
        SCAN_HOP_SLOT(s6, jb + 6)
        // last hop of the block: only store carry if next chunk exists
        v = scan_hop(v, s7);
        if (jb + 8 < NCH) {
            if (lane < 16) carry[(jb + 8) * K_ + k] = v;
#pragma unroll
            for (int q = 0; q < 4; q++) s7[q] = __ldg(base + (jb + 15) * 64 + q);
        }
        // rescale once per 8 hops (scale cancels; carries are re-normalized in replay)
        float mx = v;
#pragma unroll
        for (int o = 1; o < 16; o <<= 1)
            mx = fmaxf(mx, __shfl_xor_sync(FULLM, mx, o, 16));
        v *= __frcp_rn(mx);
    }
}

// ---------------------------------------------------------------------------
// Phase 3: replay each chunk. 2 chunks/warp, lane owns state k.
// Carry normalized ON ENTRY (sum == 1), so lZ = log(z) is exact.
// ---------------------------------------------------------------------------
__global__ __launch_bounds__(128) void k_replay(
    const float* __restrict__ em, const float* __restrict__ bp,
    const float* __restrict__ msk, float* __restrict__ out)
{
    const int gwarp = (blockIdx.x * blockDim.x + threadIdx.x) >> 5;
    const int lane  = threadIdx.x & 31;
    const int k     = lane & 15;
    const int chunk = gwarp * 2 + (lane >> 4);
    const unsigned hm = 0xffffu << (lane & 16);
    const int b  = chunk >> 7;
    const int j  = chunk & (NCH - 1);
    const int t0 = j * C_;
    const size_t bt0 = (size_t)b * T_ + t0;

    float* __restrict__ bel = out;
    float* __restrict__ lgb = out + OFF_LB;
    float* __restrict__ lgz = out + OFF_LZ;

    const float* __restrict__ embase = em + bt0 * K_;

    const float bpv0 = __ldg(bp  + bt0 + k);
    const float bpv1 = __ldg(bp  + bt0 + 16 + k);
    const float mv0  = __ldg(msk + bt0 + k);
    const float mv1  = __ldg(msk + bt0 + 16 + k);

    float er[4];
#pragma unroll
    for (int u = 0; u < 4; u++) er[u] = __ldg(embase + u * K_ + k);

    float alpha;
    if (j == 0) {
        alpha = (k == 0) ? 1.0f : 0.0f;
    } else {
        alpha = g_carry[chunk][k];
        float ss = alpha;
#pragma unroll
        for (int o = 1; o < 16; o <<= 1) ss += __shfl_xor_sync(hm, ss, o, 16);
        alpha *= __frcp_rn(ss);            // normalize carry: sum(alpha) == 1
    }

#pragma unroll 4
    for (int s = 0; s < C_; s++) {
        const float emv = er[s & 3];
        if (s + 4 < C_) er[s & 3] = __ldg(embase + (s + 4) * K_ + k);

        const size_t t = bt0 + s;
        const float bpv = __shfl_sync(hm, (s < 16) ? bpv0 : bpv1, s & 15, 16);
        const float mv  = __shfl_sync(hm, (s < 16) ? mv0  : mv1,  s & 15, 16);

        if (s == 0 && j == 0) {
            const float em00 = __shfl_sync(hm, emv, 0, 16);
            const float lb0 = (k == 0) ? 0.0f
                          : ((mv > 0.5f) ? ((-1.0e6f + emv) - em00) : -1.0e6f);
            bel[t * K_ + k] = alpha;
            lgb[t * K_ + k] = lb0;
            if (k == 0) lgz[t] = mv * em00;
            continue;
        }

        const float eta = fminf(fmaxf(fmaf(0.33f, bpv, 0.02f), 0.001f), 0.95f);
        const float d0  = 1.0f - eta;
        const float dm  = d0 - RHO;

        const float a_di = (k == 0) ? d0 : (k == 15 ? D15 : dm);

        const float am1 = __shfl_up_sync(hm, alpha, 1, 16);
        const float ap1 = __shfl_down_sync(hm, alpha, 1, 16);
        const float c_m1 = (k > 0)  ? am1 : 0.0f;
        const float c_p1 = (k < 15) ? ap1 : 0.0f;

        float pred = fmaf(c_m1, eta, CLIPV);       // background (sum(alpha)==1)
        pred = fmaf(alpha, a_di, pred);
        pred = fmaf(c_p1, RHO, pred);
        const float lj = pred * __expf(emv);

        float z = lj;
#pragma unroll
        for (int o = 1; o < 16; o <<= 1) z += __shfl_xor_sync(hm, z, o, 16);

        const float lZ = __logf(z);
        float lgbv;
        if (mv > 0.5f) {
            alpha = lj * __frcp_rn(z);
            lgbv  = __logf(alpha);
        } else {
            lgbv  = __logf(alpha);
        }

        bel[t * K_ + k] = alpha;
        lgb[t * K_ + k] = lgbv;
        if (k == 0) lgz[t] = mv * lZ;
    }
}

extern "C" void kernel_launch(void* const* d_in, const int* in_sizes, int n_in,
                              void* d_out, int out_size)
{
    const float* em  = (const float*)d_in[0];
    const float* bp  = (const float*)d_in[1];
    const float* msk = (const float*)d_in[2];
    float* out = (float*)d_out;

    k_chunkmats<<<NCHUNKS / 8, 128>>>(em, bp, out);   // 512 blocks
    k_scan<<<B_, 32>>>();
    k_replay<<<NCHUNKS / 8, 128>>>(em, bp, msk, out); // 512 blocks
}

// round 10
// speedup vs baseline: 3.0647x; 1.0429x over previous
#include <cuda_runtime.h>
#include <cstdint>

// NeuralHMM forward, B=32, T=4096, K=16 — 3-phase chunked linear-space scan.
// Phase 1 (R7-proven): C=32 chunks, 2 per warp (half-warps); composes the
//   32-step chunk matrix, writes A coalesced, and ALSO snapshots the 16-step
//   half matrix (register state after s=15) to g_halfM.
// Phase 2 (R7-proven): per-batch scan over 128 chunk matrices, depth-8
//   static pipeline; carries at chunk (32-step) granularity.
// Phase 3: replay at C=16 (8192 sub-chunks, 2/warp): even sub-chunks read the
//   chunk carry; odd sub-chunks apply one matvec with the half matrix.

#define FULLM 0xffffffffu

constexpr int B_ = 32, T_ = 4096, K_ = 16;
constexpr int C_ = 32, NCH = T_ / C_;        // 128 chunks/batch
constexpr int NCHUNKS = B_ * NCH;            // 4096
constexpr int RC = 16, NSUB = T_ / RC;       // replay sub-chunks: 256/batch
constexpr int NSUB_TOT = B_ * NSUB;          // 8192
constexpr float RHO = 0.001f;
constexpr float D15 = 1.0f - RHO;            // 0.999
constexpr float CLIPV = 1e-10f;

__device__ __align__(16) float g_chunkM[NCHUNKS][K_][K_]; // [chunk][k][i] = M[i][k] (col-major)
__device__ __align__(16) float g_halfM[NCHUNKS][K_][K_];  // 16-step half matrix, same layout
__device__ __align__(16) float g_carry[NCHUNKS][K_];      // UNNORMALIZED alpha entering chunk j>=1

constexpr size_t N_BTK = (size_t)B_ * T_ * K_;
constexpr size_t N_BT  = (size_t)B_ * T_;
constexpr size_t OFF_LB = N_BTK;
constexpr size_t OFF_LZ = 2 * N_BTK;
constexpr size_t OFF_A  = 2 * N_BTK + N_BT;

// ---------------------------------------------------------------------------
// Phase 1: chunk matrices + half-matrix snapshot + A output.
// 2 chunks/warp, lane owns row i; A written via affine coefficients.
// ---------------------------------------------------------------------------
__global__ __launch_bounds__(128) void k_chunkmats(
    const float* __restrict__ em, const float* __restrict__ bp,
    float* __restrict__ out)
{
    const int gwarp = (blockIdx.x * blockDim.x + threadIdx.x) >> 5;
    const int lane  = threadIdx.x & 31;
    const int i     = lane & 15;
    const int chunk = gwarp * 2 + (lane >> 4);
    const unsigned hm = 0xffffu << (lane & 16);
    const int b  = chunk >> 7;           // /NCH (128)
    const int j  = chunk & (NCH - 1);
    const int t0 = j * C_;
    const size_t bt0 = (size_t)b * T_ + t0;

    float4* __restrict__ A4 =
        reinterpret_cast<float4*>(out + OFF_A + bt0 * (size_t)(K_ * K_));
    const float* __restrict__ embase = em + bt0 * K_;

    // --- affine A coefficients: entry = K0 + eta*K1, per lane's 4 slots ---
    float K0[4][4], K1[4][4];
#pragma unroll
    for (int u = 0; u < 4; u++) {
        const int r  = u * 4 + (i >> 2);
        const int cg = i & 3;
#pragma unroll
        for (int q = 0; q < 4; q++) {
            const int col = cg * 4 + q;
            float k0 = 0.f, k1 = 0.f;
            if (col == r - 1) k0 += RHO;
            if (col == r) {
                if (r == 0)       { k0 += 1.0f;       k1 -= 1.0f; }
                else if (r == 15) { k0 += D15; }
                else              { k0 += 1.0f - RHO; k1 -= 1.0f; }
            }
            if (col == r + 1 && r < 15) k1 += 1.0f;
            K0[u][q] = k0; K1[u][q] = k1;
        }
    }

    // --- upfront bp (32 values per chunk via 2 regs + shfl) ---
    const float bpA = __ldg(bp + bt0 + i);
    const float bpB = __ldg(bp + bt0 + 16 + i);

    // --- em ring prefetch (lane's own k=i element), depth 4 ---
    float er[4];
#pragma unroll
    for (int u = 0; u < 4; u++) er[u] = __ldg(embase + u * K_ + i);

    float m[K_], mh[K_];
#pragma unroll
    for (int k = 0; k < K_; k++) { m[k] = (k == i) ? 1.0f : 0.0f; mh[k] = m[k]; }
    float rs = 1.0f;

#pragma unroll 4
    for (int s = 0; s < C_; s++) {
        const float emraw = er[s & 3];
        if (s + 4 < C_) er[s & 3] = __ldg(embase + (s + 4) * K_ + i);

        const float bpv = __shfl_sync(hm, (s < 16) ? bpA : bpB, s & 15, 16);
        const float eta = fminf(fmaxf(fmaf(0.33f, bpv, 0.02f), 0.001f), 0.95f);
        const float d0  = 1.0f - eta;
        const float dm  = d0 - RHO;

        // ---- A write: 4 coalesced float4 stores (256B contiguous/half-warp) ----
#pragma unroll
        for (int u = 0; u < 4; u++) {
            float4 w;
            w.x = fmaf(eta, K1[u][0], K0[u][0]);
            w.y = fmaf(eta, K1[u][1], K0[u][1]);
            w.z = fmaf(eta, K1[u][2], K0[u][2]);
            w.w = fmaf(eta, K1[u][3], K0[u][3]);
            __stcs(A4 + s * 64 + u * 16 + i, w);
        }

        // ---- compose (t=0 is init, not a transition) ----
        if (t0 + s > 0) {
            const float e_own = __expf(emraw);
            const float bg    = CLIPV * rs;   // background (rel err <= 3e-7)
            float rs_new = 0.0f, prev = 0.0f;
#pragma unroll
            for (int k = 0; k < 16; k++) {
                const float cur = m[k];
                const float nxt = (k < 15) ? m[k + 1] : 0.0f;
                float v;
                if (k == 0)       v = fmaf(cur, d0, bg);
                else if (k == 15) v = fmaf(prev, eta, fmaf(cur, D15, bg));
                else              v = fmaf(prev, eta, fmaf(cur, dm, bg));
                if (k < 15)       v = fmaf(nxt, RHO, v);
                v *= __shfl_sync(hm, e_own, k, 16);
                m[k] = v;
                rs_new += v;
                prev = cur;
            }
            rs = rs_new;
            if ((s & 7) == 7) {
                float mx = m[0];
#pragma unroll
                for (int k = 1; k < 16; k++) mx = fmaxf(mx, m[k]);
#pragma unroll
                for (int o = 1; o < 16; o <<= 1)
                    mx = fmaxf(mx, __shfl_xor_sync(hm, mx, o, 16));
                const float sc = __frcp_rn(mx);
#pragma unroll
                for (int k = 0; k < 16; k++) m[k] *= sc;
                rs *= sc;
            }
        }

        // ---- snapshot half matrix (state after step s=15) ----
        if (s == 15) {
#pragma unroll
            for (int k = 0; k < 16; k++) mh[k] = m[k];
        }
    }

    float* dstM = &g_chunkM[chunk][0][0];
    float* dstH = &g_halfM[chunk][0][0];
#pragma unroll
    for (int k = 0; k < 16; k++) {
        dstM[k * 16 + i] = m[k];
        dstH[k * 16 + i] = mh[k];
    }
}

// ---------------------------------------------------------------------------
// Phase 2: per-batch scan over 128 chunk matrices (one warp per batch).
// Depth-8 static software pipeline (covers L2 latency). (R7-proven)
// ---------------------------------------------------------------------------
__device__ __forceinline__ float scan_hop(float v, const float4* c)
{
    float a0 = 0.f, a1 = 0.f, a2 = 0.f, a3 = 0.f;
    a0 = fmaf(__shfl_sync(FULLM, v, 0,  16), c[0].x, a0);
    a0 = fmaf(__shfl_sync(FULLM, v, 1,  16), c[0].y, a0);
    a0 = fmaf(__shfl_sync(FULLM, v, 2,  16), c[0].z, a0);
    a0 = fmaf(__shfl_sync(FULLM, v, 3,  16), c[0].w, a0);
    a1 = fmaf(__shfl_sync(FULLM, v, 4,  16), c[1].x, a1);
    a1 = fmaf(__shfl_sync(FULLM, v, 5,  16), c[1].y, a1);
    a1 = fmaf(__shfl_sync(FULLM, v, 6,  16), c[1].z, a1);
    a1 = fmaf(__shfl_sync(FULLM, v, 7,  16), c[1].w, a1);
    a2 = fmaf(__shfl_sync(FULLM, v, 8,  16), c[2].x, a2);
    a2 = fmaf(__shfl_sync(FULLM, v, 9,  16), c[2].y, a2);
    a2 = fmaf(__shfl_sync(FULLM, v, 10, 16), c[2].z, a2);
    a2 = fmaf(__shfl_sync(FULLM, v, 11, 16), c[2].w, a2);
    a3 = fmaf(__shfl_sync(FULLM, v, 12, 16), c[3].x, a3);
    a3 = fmaf(__shfl_sync(FULLM, v, 13, 16), c[3].y, a3);
    a3 = fmaf(__shfl_sync(FULLM, v, 14, 16), c[3].z, a3);
    a3 = fmaf(__shfl_sync(FULLM, v, 15, 16), c[3].w, a3);
    return (a0 + a1) + (a2 + a3);
}

#define SCAN_HOP_SLOT(S, J)                                                    \
    v = scan_hop(v, S);                                                        \
    if (lane < 16) carry[((J) + 1) * K_ + k] = v;                              \
    if ((J) + 8 < NCH) {                                                       \
        _Pragma("unroll")                                                      \
        for (int q = 0; q < 4; q++) S[q] = __ldg(base + ((J) + 8) * 64 + q);   \
    }

__global__ void k_scan()
{
    const int b    = blockIdx.x;
    const int lane = threadIdx.x;
    const int k    = lane & 15;

    const float4* __restrict__ base =
        reinterpret_cast<const float4*>(&g_chunkM[(size_t)b * NCH][0][0]) + k * 4;

    float4 s0[4], s1[4], s2[4], s3[4], s4[4], s5[4], s6[4], s7[4];
#pragma unroll
    for (int q = 0; q < 4; q++) {
        s0[q] = __ldg(base + 0 * 64 + q);
        s1[q] = __ldg(base + 1 * 64 + q);
        s2[q] = __ldg(base + 2 * 64 + q);
        s3[q] = __ldg(base + 3 * 64 + q);
        s4[q] = __ldg(base + 4 * 64 + q);
        s5[q] = __ldg(base + 5 * 64 + q);
        s6[q] = __ldg(base + 6 * 64 + q);
        s7[q] = __ldg(base + 7 * 64 + q);
    }

    float v = (k == 0) ? 1.0f : 0.0f;
    float* __restrict__ carry = &g_carry[(size_t)b * NCH][0];

    for (int jb = 0; jb < NCH; jb += 8) {
        SCAN_HOP_SLOT(s0, jb + 0)
        SCAN_HOP_SLOT(s1, jb + 1)
        SCAN_HOP_SLOT(s2, jb + 2)
        SCAN_HOP_SLOT(s3, jb + 3)
        SCAN_HOP_SLOT(s4, jb + 4)
        SCAN_HOP_SLOT(s5, jb + 5)
        SCAN_HOP_SLOT(s6, jb + 6)
        v = scan_hop(v, s7);
        if (jb + 8 < NCH) {
            if (lane < 16) carry[(jb + 8) * K_ + k] = v;
#pragma unroll
            for (int q = 0; q < 4; q++) s7[q] = __ldg(base + (jb + 15) * 64 + q);
        }
        float mx = v;
#pragma unroll
        for (int o = 1; o < 16; o <<= 1)
            mx = fmaxf(mx, __shfl_xor_sync(FULLM, mx, o, 16));
        v *= __frcp_rn(mx);
    }
}

// ---------------------------------------------------------------------------
// Phase 3: replay at RC=16. 2 sub-chunks/warp (half-warps), lane owns state k.
// Even sub-chunk 2p: carry = g_carry[p] (onehot for p=0). Odd sub-chunk 2p+1:
// carry = (p==0 ? onehot : g_carry[p]) * halfM[p]. Normalized on entry.
// ---------------------------------------------------------------------------
__global__ __launch_bounds__(128) void k_replay(
    const float* __restrict__ em, const float* __restrict__ bp,
    const float* __restrict__ msk, float* __restrict__ out)
{
    const int gwarp = (blockIdx.x * blockDim.x + threadIdx.x) >> 5;
    const int lane  = threadIdx.x & 31;
    const int k     = lane & 15;
    const int c     = gwarp * 2 + (lane >> 4);
    const unsigned hm = 0xffffu << (lane & 16);
    const int b  = c >> 8;               // /NSUB (256)
    const int jc = c & (NSUB - 1);
    const int pj = jc >> 1;              // parent chunk (C=32)
    const size_t bt0 = (size_t)b * T_ + jc * RC;

    float* __restrict__ bel = out;
    float* __restrict__ lgb = out + OFF_LB;
    float* __restrict__ lgz = out + OFF_LZ;

    const float* __restrict__ embase = em + bt0 * K_;

    const float bpv0 = __ldg(bp  + bt0 + k);
    const float mv0  = __ldg(msk + bt0 + k);

    float er[4];
#pragma unroll
    for (int u = 0; u < 4; u++) er[u] = __ldg(embase + u * K_ + k);

    float alpha;
    if (jc == 0) {
        alpha = (k == 0) ? 1.0f : 0.0f;
    } else {
        if (jc & 1) {
            // odd: alpha = carry(pair pj) * halfM[pj]   (column k dot)
            const float v = (pj == 0) ? ((k == 0) ? 1.0f : 0.0f)
                                      : g_carry[b * NCH + pj][k];
            const float4* hc =
                reinterpret_cast<const float4*>(&g_halfM[b * NCH + pj][k][0]);
            const float4 c0 = __ldg(hc + 0), c1 = __ldg(hc + 1);
            const float4 c2 = __ldg(hc + 2), c3 = __ldg(hc + 3);
            float a0 = 0.f, a1 = 0.f, a2 = 0.f, a3 = 0.f;
            a0 = fmaf(__shfl_sync(hm, v, 0,  16), c0.x, a0);
            a0 = fmaf(__shfl_sync(hm, v, 1,  16), c0.y, a0);
            a0 = fmaf(__shfl_sync(hm, v, 2,  16), c0.z, a0);
            a0 = fmaf(__shfl_sync(hm, v, 3,  16), c0.w, a0);
            a1 = fmaf(__shfl_sync(hm, v, 4,  16), c1.x, a1);
            a1 = fmaf(__shfl_sync(hm, v, 5,  16), c1.y, a1);
            a1 = fmaf(__shfl_sync(hm, v, 6,  16), c1.z, a1);
            a1 = fmaf(__shfl_sync(hm, v, 7,  16), c1.w, a1);
            a2 = fmaf(__shfl_sync(hm, v, 8,  16), c2.x, a2);
            a2 = fmaf(__shfl_sync(hm, v, 9,  16), c2.y, a2);
            a2 = fmaf(__shfl_sync(hm, v, 10, 16), c2.z, a2);
            a2 = fmaf(__shfl_sync(hm, v, 11, 16), c2.w, a2);
            a3 = fmaf(__shfl_sync(hm, v, 12, 16), c3.x, a3);
            a3 = fmaf(__shfl_sync(hm, v, 13, 16), c3.y, a3);
            a3 = fmaf(__shfl_sync(hm, v, 14, 16), c3.z, a3);
            a3 = fmaf(__shfl_sync(hm, v, 15, 16), c3.w, a3);
            alpha = (a0 + a1) + (a2 + a3);
        } else {
            alpha = g_carry[b * NCH + pj][k];
        }
        float ss = alpha;
#pragma unroll
        for (int o = 1; o < 16; o <<= 1) ss += __shfl_xor_sync(hm, ss, o, 16);
        alpha *= __frcp_rn(ss);            // normalize: sum(alpha) == 1
    }

#pragma unroll 4
    for (int s = 0; s < RC; s++) {
        const float emv = er[s & 3];
        if (s + 4 < RC) er[s & 3] = __ldg(embase + (s + 4) * K_ + k);

        const size_t t = bt0 + s;
        const float bpv = __shfl_sync(hm, bpv0, s, 16);
        const float mv  = __shfl_sync(hm, mv0,  s, 16);

        if (s == 0 && jc == 0) {
            const float em00 = __shfl_sync(hm, emv, 0, 16);
            const float lb0 = (k == 0) ? 0.0f
                          : ((mv > 0.5f) ? ((-1.0e6f + emv) - em00) : -1.0e6f);
            bel[t * K_ + k] = alpha;
            lgb[t * K_ + k] = lb0;
            if (k == 0) lgz[t] = mv * em00;
            continue;
        }

        const float eta = fminf(fmaxf(fmaf(0.33f, bpv, 0.02f), 0.001f), 0.95f);
        const float d0  = 1.0f - eta;
        const float dm  = d0 - RHO;

        const float a_di = (k == 0) ? d0 : (k == 15 ? D15 : dm);

        const float am1 = __shfl_up_sync(hm, alpha, 1, 16);
        const float ap1 = __shfl_down_sync(hm, alpha, 1, 16);
        const float c_m1 = (k > 0)  ? am1 : 0.0f;
        const float c_p1 = (k < 15) ? ap1 : 0.0f;

        float pred = fmaf(c_m1, eta, CLIPV);       // background (sum(alpha)==1)
        pred = fmaf(alpha, a_di, pred);
        pred = fmaf(c_p1, RHO, pred);
        const float lj = pred * __expf(emv);

        float z = lj;
#pragma unroll
        for (int o = 1; o < 16; o <<= 1) z += __shfl_xor_sync(hm, z, o, 16);

        const float lZ = __logf(z);
        float lgbv;
        if (mv > 0.5f) {
            alpha = lj * __frcp_rn(z);
            lgbv  = __logf(alpha);
        } else {
            lgbv  = __logf(alpha);
        }

        bel[t * K_ + k] = alpha;
        lgb[t * K_ + k] = lgbv;
        if (k == 0) lgz[t] = mv * lZ;
    }
}

extern "C" void kernel_launch(void* const* d_in, const int* in_sizes, int n_in,
                              void* d_out, int out_size)
{
    const float* em  = (const float*)d_in[0];
    const float* bp  = (const float*)d_in[1];
    const float* msk = (const float*)d_in[2];
    float* out = (float*)d_out;

    k_chunkmats<<<NCHUNKS / 8, 128>>>(em, bp, out);   // 512 blocks (R7-proven)
    k_scan<<<B_, 32>>>();
    k_replay<<<NSUB_TOT / 8, 128>>>(em, bp, msk, out); // 1024 blocks, RC=16
}